// round 13
// baseline (speedup 1.0000x reference)
#include <cuda_runtime.h>
#include <cuda_bf16.h>
#include <math.h>
#include <float.h>
#include <stdint.h>

#define NPART 62
#define MM    512
#define DD    256
#define MARGIN 0.2f
#define NTILE 36           // pairs (a<=b) of 8 groups of 64
#define NSLOT 9            // CTAs per part; each does 4 tiles
#define RSLOT 57           // rows converted per CTA (9*57 >= 512)

// smem: 2 buffers x 4 planes x (64 rows x 64B, XOR-swizzled) + scratch
#define PLANE   4096       // 64 * 64
#define BUFSZ   16384      // 4 planes
#define SM_SQ     32768    // 128 floats
#define SM_ROWMIN 33280    // 64*2 f
#define SM_ROWMAX 33792    // 64*2 f
#define SM_COLMIN 34304    // 64*2 f
#define SM_RSUM   34816    // scratch (wsum / flag / finish)
#define SM_TOTAL  35328

// global scratch (no allocation allowed)
__device__ float g_min[NPART * 64 * 64];     // slot-owned mins (no init needed)
__device__ float g_hp[NPART * MM];           // written only by diagonal CTAs
__device__ float g_dsum[NPART * NTILE];      // per-tile dist sums (fixed order)
__device__ int   g_cnt[NPART];               // tile-CTA arrival counters
__device__ int   g_prep[NPART];              // prep-slice completion counters
__device__ __align__(16) __nv_bfloat16 g_hi[(size_t)NPART * MM * DD];
__device__ __align__(16) __nv_bfloat16 g_lo[(size_t)NPART * MM * DD];
__device__ __align__(16) float g_sq[NPART * MM];

__device__ __forceinline__ uint32_t smem_u32(const void* p) {
    uint32_t a;
    asm("{ .reg .u64 t; cvta.to.shared.u64 t, %1; cvt.u32.u64 %0, t; }" : "=r"(a) : "l"(p));
    return a;
}
__device__ __forceinline__ void cp16(uint32_t dst, const void* src) {
    asm volatile("cp.async.cg.shared.global [%0], [%1], 16;" :: "r"(dst), "l"(src));
}
#define CP_COMMIT() asm volatile("cp.async.commit_group;" ::: "memory")
#define CP_WAIT(n)  asm volatile("cp.async.wait_group %0;" :: "n"(n) : "memory")

__device__ __forceinline__ void ldm_x4(uint32_t* r, uint32_t addr) {
    asm volatile("ldmatrix.sync.aligned.m8n8.x4.shared.b16 {%0,%1,%2,%3}, [%4];"
                 : "=r"(r[0]), "=r"(r[1]), "=r"(r[2]), "=r"(r[3]) : "r"(addr));
}
__device__ __forceinline__ void mma16816(float* c, const uint32_t* a, const uint32_t* b) {
    asm volatile("mma.sync.aligned.m16n8k16.row.col.f32.bf16.bf16.f32 "
                 "{%0,%1,%2,%3}, {%4,%5,%6,%7}, {%8,%9}, {%0,%1,%2,%3};"
                 : "+f"(c[0]), "+f"(c[1]), "+f"(c[2]), "+f"(c[3])
                 : "r"(a[0]), "r"(a[1]), "r"(a[2]), "r"(a[3]), "r"(b[0]), "r"(b[1]));
}
__device__ __forceinline__ void tile_pair(int t, int& a, int& b) {
    int aa = 0, tt = t;
    while (tt >= 8 - aa) { tt -= 8 - aa; aa++; }
    a = aa; b = aa + tt;
}

// ---------------------------------------------------------------------------
// Persistent single-wave kernel. grid (9, 62) = 558 CTAs, all resident
// (capacity 148*6 = 888; safe even at occupancy 4). Phases per CTA:
//   1. convert: split-bf16 + exact sq for its 57-row slice of part n
//      (pair-masked shuffle: slot 8 has a partial warp!)
//   2. release counter; acquire-spin until all 9 slices of part n done
//      (deadlock-free: every producer is resident in the single wave)
//   3. four GEMM tiles (slot, slot+9, +18, +27) — proven R11 pipeline
//   4. last CTA of part n computes the final outputs, resets counters
// ---------------------------------------------------------------------------
__global__ void __launch_bounds__(128, 6) fused_kernel(const float* __restrict__ f,
                                                       float* __restrict__ out) {
    extern __shared__ char smem[];
    uint32_t sb = smem_u32(smem);
    const int tid  = threadIdx.x;
    const int wid  = tid >> 5;
    const int lane = tid & 31;
    const int wr = wid >> 1;
    const int wc = wid & 1;
    const int slot = blockIdx.x;
    const int n    = blockIdx.y;

    // ---- phase 1: convert slice [slot*57, slot*57+nr) ----
    {
        const int r0 = slot * RSLOT;
        const int nr = (r0 + RSLOT <= MM) ? RSLOT : (MM - r0);
        if ((tid >> 1) < nr) {
            const int h = tid & 1;
            const size_t row = (size_t)n * MM + r0 + (tid >> 1);
            const float4* src = (const float4*)(f + row * DD + h * 128);
            const size_t off0 = row * DD + h * 128;
            float s = 0.f;
#pragma unroll 8
            for (int i = 0; i < 32; i++) {
                float4 v = src[i];
                __nv_bfloat162 h01 = __floats2bfloat162_rn(v.x, v.y);
                __nv_bfloat162 h23 = __floats2bfloat162_rn(v.z, v.w);
                float2 f01 = __bfloat1622float2(h01);
                float2 f23 = __bfloat1622float2(h23);
                __nv_bfloat162 l01 = __floats2bfloat162_rn(v.x - f01.x, v.y - f01.y);
                __nv_bfloat162 l23 = __floats2bfloat162_rn(v.z - f23.x, v.w - f23.y);
                size_t off = off0 + i * 4;
                *(uint2*)(g_hi + off) = make_uint2(*(uint32_t*)&h01, *(uint32_t*)&h23);
                *(uint2*)(g_lo + off) = make_uint2(*(uint32_t*)&l01, *(uint32_t*)&l23);
                s += v.x * v.x + v.y * v.y + v.z * v.z + v.w * v.w;
            }
            // pair-wise reduce: membermask = exactly the (l, l^1) pair —
            // full-warp mask here deadlocks on slot 8's partial warp.
            s += __shfl_xor_sync(0x3u << (lane & 30), s, 1);
            if (h == 0) g_sq[row] = s;
        }
        __syncthreads();
        if (tid == 0) {
            __threadfence();
            atomicAdd(&g_prep[n], 1);
        }
    }

    // ---- phase 2: wait for the whole part ----
    if (tid == 0) {
        int v;
        do {
            asm volatile("ld.global.acquire.gpu.b32 %0, [%1];"
                         : "=r"(v) : "l"(&g_prep[n]) : "memory");
            if (v != NSLOT) __nanosleep(32);
        } while (v != NSLOT);
    }
    __syncthreads();

    const __nv_bfloat16* hi_n = g_hi + (size_t)n * MM * DD;
    const __nv_bfloat16* lo_n = g_lo + (size_t)n * MM * DD;

    // per-lane ldmatrix swizzle constants (tile-invariant)
    const int la = lane & 15;
    const uint32_t aro = (uint32_t)la * 64;
    const int xa = (la >> 1) & 3;
    const int pa = lane >> 4;
    const uint32_t cxa0 = (uint32_t)((pa ^ xa) & 3) << 4;
    const uint32_t cxa1 = (uint32_t)(((2 + pa) ^ xa) & 3) << 4;
    const int rb = (lane & 7) + ((lane >> 4) & 1) * 8;
    const uint32_t bro = (uint32_t)rb * 64;
    const int xb = (rb >> 1) & 3;
    const int pb = (lane >> 3) & 1;
    const uint32_t cxb0 = (uint32_t)((pb ^ xb) & 3) << 4;
    const uint32_t cxb1 = (uint32_t)(((2 + pb) ^ xb) & 3) << 4;

    float* rowmin = (float*)(smem + SM_ROWMIN);
    float* rowmax = (float*)(smem + SM_ROWMAX);
    float* colmin = (float*)(smem + SM_COLMIN);
    float* scratch = (float*)(smem + SM_RSUM);

    // ---- phase 3: four tiles ----
#pragma unroll 1
    for (int j = 0; j < 4; j++) {
        const int t = slot + j * NSLOT;
        int a, b; tile_pair(t, a, b);
        const bool diag = (a == b);
        const int nload = diag ? 512 : 1024;
        const uint32_t bplane = diag ? 0u : 2u * PLANE;

        // prologue: sq + k-chunk 0
        if (tid < 32) {
            int grp = (tid < 16) ? a : b;
            int q = tid & 15;
            cp16(sb + SM_SQ + tid * 16, g_sq + n * MM + grp * 64 + q * 4);
        }
        for (int c = tid; c < nload; c += 128) {
            int plane = c >> 8, idx = c & 255;
            int r = idx >> 2, q = idx & 3;
            int grp = (plane < 2) ? a : b;
            const __nv_bfloat16* src =
                ((plane & 1) ? lo_n : hi_n) + (size_t)(grp * 64 + r) * DD + q * 8;
            cp16(sb + plane * PLANE + r * 64 + (((q ^ (r >> 1)) & 3) << 4), src);
        }
        CP_COMMIT();

        float acc[2][4][4];
#pragma unroll
        for (int mi = 0; mi < 2; mi++)
#pragma unroll
            for (int ni = 0; ni < 4; ni++)
#pragma unroll
                for (int r = 0; r < 4; r++) acc[mi][ni][r] = 0.f;

#pragma unroll 1
        for (int s = 0; s < 8; s++) {
            if (s < 7) {
                const int k0 = (s + 1) * 32;
                const uint32_t bufn = (uint32_t)((s + 1) & 1) * BUFSZ;
                for (int c = tid; c < nload; c += 128) {
                    int plane = c >> 8, idx = c & 255;
                    int r = idx >> 2, q = idx & 3;
                    int grp = (plane < 2) ? a : b;
                    const __nv_bfloat16* src =
                        ((plane & 1) ? lo_n : hi_n) + (size_t)(grp * 64 + r) * DD + k0 + q * 8;
                    cp16(sb + bufn + plane * PLANE + r * 64 + (((q ^ (r >> 1)) & 3) << 4), src);
                }
                CP_COMMIT();
                CP_WAIT(1);
            } else {
                CP_WAIT(0);
            }
            __syncthreads();

            const uint32_t bufb = sb + (uint32_t)(s & 1) * BUFSZ;
#pragma unroll
            for (int ks = 0; ks < 2; ks++) {
                const uint32_t cxa = ks ? cxa1 : cxa0;
                const uint32_t cxb = ks ? cxb1 : cxb0;
                uint32_t ahi[2][4], alo[2][4], bhi[2][4], blo[2][4];
#pragma unroll
                for (int mi = 0; mi < 2; mi++) {
                    uint32_t ra = bufb + (uint32_t)(wr * 32 + mi * 16) * 64 + aro + cxa;
                    ldm_x4(ahi[mi], ra);
                    ldm_x4(alo[mi], ra + PLANE);
                }
#pragma unroll
                for (int g = 0; g < 2; g++) {
                    uint32_t rbad = bufb + bplane + (uint32_t)(wc * 32 + g * 16) * 64 + bro + cxb;
                    ldm_x4(bhi[g], rbad);
                    ldm_x4(blo[g], rbad + PLANE);
                }
#pragma unroll
                for (int mi = 0; mi < 2; mi++)
#pragma unroll
                    for (int ni = 0; ni < 4; ni++) {
                        const int g = ni >> 1, o = (ni & 1) * 2;
                        mma16816(acc[mi][ni], ahi[mi], &bhi[g][o]);
                        mma16816(acc[mi][ni], ahi[mi], &blo[g][o]);
                        mma16816(acc[mi][ni], alo[mi], &bhi[g][o]);
                    }
            }
            __syncthreads();
        }

        // epilogue
        const float* sq_s = (const float*)(smem + SM_SQ);
        float rmin[4], rmax[4], cmin[8];
#pragma unroll
        for (int i = 0; i < 4; i++) { rmin[i] = FLT_MAX; rmax[i] = -FLT_MAX; }
#pragma unroll
        for (int i = 0; i < 8; i++) cmin[i] = FLT_MAX;
        float dsum = 0.f;

#pragma unroll
        for (int mi = 0; mi < 2; mi++)
#pragma unroll
            for (int ni = 0; ni < 4; ni++)
#pragma unroll
                for (int r = 0; r < 4; r++) {
                    const int rowl = wr * 32 + mi * 16 + (r >> 1) * 8 + (lane >> 2);
                    const int col  = wc * 32 + ni * 8 + (lane & 3) * 2 + (r & 1);
                    float d2 = sq_s[rowl] + sq_s[64 + col] - 2.f * acc[mi][ni][r];
                    float dist = sqrtf(fmaxf(d2, 0.f));
                    dsum += dist;
                    const int rs = mi * 2 + (r >> 1);
                    const int cs = ni * 2 + (r & 1);
                    if (diag) {
                        if ((rowl >> 3) == (col >> 3)) rmax[rs] = fmaxf(rmax[rs], dist);
                        else                           rmin[rs] = fminf(rmin[rs], dist);
                    } else {
                        rmin[rs] = fminf(rmin[rs], dist);
                        cmin[cs] = fminf(cmin[cs], dist);
                    }
                }

#pragma unroll
        for (int s2 = 0; s2 < 4; s2++) {
            float rm = rmin[s2], rx = rmax[s2];
            rm = fminf(rm, __shfl_xor_sync(0xFFFFFFFFu, rm, 1));
            rm = fminf(rm, __shfl_xor_sync(0xFFFFFFFFu, rm, 2));
            rx = fmaxf(rx, __shfl_xor_sync(0xFFFFFFFFu, rx, 1));
            rx = fmaxf(rx, __shfl_xor_sync(0xFFFFFFFFu, rx, 2));
            if ((lane & 3) == 0) {
                const int row = wr * 32 + (s2 >> 1) * 16 + (s2 & 1) * 8 + (lane >> 2);
                rowmin[row * 2 + wc] = rm;
                rowmax[row * 2 + wc] = rx;
            }
        }
#pragma unroll
        for (int s2 = 0; s2 < 8; s2++) {
            float cm = cmin[s2];
            cm = fminf(cm, __shfl_xor_sync(0xFFFFFFFFu, cm, 4));
            cm = fminf(cm, __shfl_xor_sync(0xFFFFFFFFu, cm, 8));
            cm = fminf(cm, __shfl_xor_sync(0xFFFFFFFFu, cm, 16));
            if (lane < 4) {
                const int col = wc * 32 + (s2 >> 1) * 8 + (lane & 3) * 2 + (s2 & 1);
                colmin[col * 2 + wr] = cm;
            }
        }
#pragma unroll
        for (int o = 16; o; o >>= 1) dsum += __shfl_xor_sync(0xFFFFFFFFu, dsum, o);
        if (lane == 0) scratch[wid] = dsum;
        __syncthreads();

        if (tid < 64) {
            float rn = fminf(rowmin[tid * 2], rowmin[tid * 2 + 1]);
            float rp = fmaxf(rowmax[tid * 2], rowmax[tid * 2 + 1]);
            g_min[(n * 64 + a * 8 + b) * 64 + tid] = rn;   // slot b of group a
            if (diag) g_hp[n * MM + a * 64 + tid] = rp;
        } else {
            if (!diag) {
                const int jj = tid - 64;
                float cm = fminf(colmin[jj * 2], colmin[jj * 2 + 1]);
                g_min[(n * 64 + b * 8 + a) * 64 + jj] = cm; // slot a of group b
            }
        }
        if (tid == 0)
            g_dsum[n * NTILE + t] = (scratch[0] + scratch[1]) + (scratch[2] + scratch[3]);
        __syncthreads();
    }

    // ---- phase 4: last CTA of the part computes outputs ----
    int* flag = (int*)(scratch + 4);
    if (tid == 0) {
        __threadfence();
        int prev = atomicAdd(&g_cnt[n], 1);
        *flag = (prev == NSLOT - 1);
    }
    __syncthreads();
    if (!*flag) return;
    __threadfence();

    float l = 0.f;
#pragma unroll
    for (int h = 0; h < 4; h++) {
        const int row = tid + h * 128;
        const int g = row >> 6, jj = row & 63;
        float mn = FLT_MAX;
#pragma unroll
        for (int s = 0; s < 8; s++)
            mn = fminf(mn, g_min[(n * 64 + g * 8 + s) * 64 + jj]);
        l += fmaxf(MARGIN + g_hp[n * MM + row] - mn, 0.f);
    }
#pragma unroll
    for (int o = 16; o; o >>= 1) l += __shfl_xor_sync(0xFFFFFFFFu, l, o);
    if (lane == 0) scratch[wid] = l;
    if (tid < NTILE) {
        int aa, bb; tile_pair(tid, aa, bb);
        scratch[8 + tid] = g_dsum[n * NTILE + tid] * ((aa == bb) ? 1.f : 2.f);
    }
    __syncthreads();
    if (tid == 0) {
        float ls = (scratch[0] + scratch[1]) + (scratch[2] + scratch[3]);
        float d = 0.f;
#pragma unroll
        for (int i = 0; i < NTILE; i++) d += scratch[8 + i];
        out[n]         = ls / (float)MM;
        out[NPART + n] = d / ((float)MM * (float)MM);
        g_cnt[n] = 0;    // reset for next graph replay
        g_prep[n] = 0;
    }
}

extern "C" void kernel_launch(void* const* d_in, const int* in_sizes, int n_in,
                              void* d_out, int out_size) {
    const float* feature = (const float*)d_in[0];
    float* out = (float*)d_out;

    cudaFuncSetAttribute(fused_kernel, cudaFuncAttributeMaxDynamicSharedMemorySize, SM_TOTAL);

    dim3 grid(NSLOT, NPART);
    fused_kernel<<<grid, 128, SM_TOTAL>>>(feature, out);
}

// round 14
// speedup vs baseline: 1.6099x; 1.6099x over previous
#include <cuda_runtime.h>
#include <cuda_bf16.h>
#include <math.h>
#include <float.h>
#include <stdint.h>

#define NPART 62
#define MM    512
#define DD    256
#define MARGIN 0.2f
#define NTILE 36           // pairs (a<=b) of 8 groups of 64

// smem: 2 buffers x 4 planes x (64 rows x 64B, XOR-swizzled) + scratch
#define PLANE   4096       // 64 * 64
#define BUFSZ   16384      // 4 planes
#define SM_SQ     32768    // 128 floats
#define SM_ROWMIN 33280    // 64*2 f
#define SM_ROWMAX 33792    // 64*2 f
#define SM_COLMIN 34304    // 64*2 f
#define SM_RSUM   34816    // scratch (wsum / flag / finish)
#define SM_TOTAL  35328

// global scratch (no allocation allowed)
__device__ float g_min[NPART * 64 * 64];     // slot-owned mins (no init needed)
__device__ float g_hp[NPART * MM];           // written only by diagonal CTAs
__device__ float g_dsum[NPART * NTILE];      // per-tile dist sums (fixed order)
__device__ int   g_cnt[NPART];               // arrival counters (reset by last CTA)
__device__ __align__(16) __nv_bfloat16 g_hi[(size_t)NPART * MM * DD];
__device__ __align__(16) __nv_bfloat16 g_lo[(size_t)NPART * MM * DD];
__device__ __align__(16) float g_sq[NPART * MM];

__device__ __forceinline__ uint32_t smem_u32(const void* p) {
    uint32_t a;
    asm("{ .reg .u64 t; cvta.to.shared.u64 t, %1; cvt.u32.u64 %0, t; }" : "=r"(a) : "l"(p));
    return a;
}
__device__ __forceinline__ void cp16(uint32_t dst, const void* src) {
    asm volatile("cp.async.cg.shared.global [%0], [%1], 16;" :: "r"(dst), "l"(src));
}
#define CP_COMMIT() asm volatile("cp.async.commit_group;" ::: "memory")
#define CP_WAIT(n)  asm volatile("cp.async.wait_group %0;" :: "n"(n) : "memory")

__device__ __forceinline__ void ldm_x4(uint32_t* r, uint32_t addr) {
    asm volatile("ldmatrix.sync.aligned.m8n8.x4.shared.b16 {%0,%1,%2,%3}, [%4];"
                 : "=r"(r[0]), "=r"(r[1]), "=r"(r[2]), "=r"(r[3]) : "r"(addr));
}
__device__ __forceinline__ void mma16816(float* c, const uint32_t* a, const uint32_t* b) {
    asm volatile("mma.sync.aligned.m16n8k16.row.col.f32.bf16.bf16.f32 "
                 "{%0,%1,%2,%3}, {%4,%5,%6,%7}, {%8,%9}, {%0,%1,%2,%3};"
                 : "+f"(c[0]), "+f"(c[1]), "+f"(c[2]), "+f"(c[3])
                 : "r"(a[0]), "r"(a[1]), "r"(a[2]), "r"(a[3]), "r"(b[0]), "r"(b[1]));
}
__device__ __forceinline__ void tile_pair(int t, int& a, int& b) {
    int aa = 0, tt = t;
    while (tt >= 8 - aa) { tt -= 8 - aa; aa++; }
    a = aa; b = aa + tt;
}

// ---------------------------------------------------------------------------
// Kernel 1: per row: exact fp32 sq-norm + split-bf16 hi/lo planes (8B stores).
// ---------------------------------------------------------------------------
__global__ void prep_kernel(const float* __restrict__ f) {
    int row = blockIdx.x * blockDim.y + threadIdx.y;
    if (row >= NPART * MM) return;
    int lane = threadIdx.x;
    const float4* p = (const float4*)(f + (size_t)row * DD);
    float s = 0.f;
#pragma unroll
    for (int q = 0; q < 2; q++) {
        float4 v = p[lane + q * 32];
        int col = (lane + q * 32) * 4;
        __nv_bfloat162 h01 = __floats2bfloat162_rn(v.x, v.y);
        __nv_bfloat162 h23 = __floats2bfloat162_rn(v.z, v.w);
        float2 f01 = __bfloat1622float2(h01);
        float2 f23 = __bfloat1622float2(h23);
        __nv_bfloat162 l01 = __floats2bfloat162_rn(v.x - f01.x, v.y - f01.y);
        __nv_bfloat162 l23 = __floats2bfloat162_rn(v.z - f23.x, v.w - f23.y);
        size_t off = (size_t)row * DD + col;
        *(uint2*)(g_hi + off) = make_uint2(*(uint32_t*)&h01, *(uint32_t*)&h23);
        *(uint2*)(g_lo + off) = make_uint2(*(uint32_t*)&l01, *(uint32_t*)&l23);
        s += v.x * v.x + v.y * v.y + v.z * v.z + v.w * v.w;
    }
#pragma unroll
    for (int o = 16; o; o >>= 1) s += __shfl_xor_sync(0xFFFFFFFFu, s, o);
    if (lane == 0) g_sq[row] = s;
}

// ---------------------------------------------------------------------------
// Kernel 2: CTA = (tile pair (a,b), part n). 4 warps x 32x32 tiles, K=256 in
// 8 chunks, the proven 2-stage prefetch-before-wait(1) pipeline, XOR swizzle
// (6 CTAs/SM). cp.async addressing fully hoisted: per thread 4 global base
// pointers + 1 smem base; the mainloop issues 8 cp16s with literal offsets.
// ---------------------------------------------------------------------------
__global__ void __launch_bounds__(128, 6) gemm_kernel(float* __restrict__ out) {
    extern __shared__ char smem[];
    uint32_t sb = smem_u32(smem);
    const int tid  = threadIdx.x;
    const int wid  = tid >> 5;
    const int lane = tid & 31;
    const int wr = wid >> 1;
    const int wc = wid & 1;
    const int t = blockIdx.x;
    const int n = blockIdx.y;
    int a, b; tile_pair(t, a, b);
    const bool diag = (a == b);

    const __nv_bfloat16* hi_n = g_hi + (size_t)n * MM * DD;
    const __nv_bfloat16* lo_n = g_lo + (size_t)n * MM * DD;

    // hoisted cp.async addressing:
    //   slot i (0..7): plane = i>>1 (Ahi,Alo,Bhi,Blo), row = tid>>2 + (i&1)*32
    //   q = tid&3 (i-invariant), swizzle = (((tid&3)^(tid>>3))&3)<<4 (i-invariant)
    //   smem dst  = base_dst + i*2048 (+ buffer)
    //   gmem src  = {hiA,loA,hiB,loB}[plane] + (i&1)*32*DD + k0
    const uint32_t base_dst = sb + (uint32_t)(tid >> 2) * 64
                            + ((((uint32_t)tid & 3) ^ ((uint32_t)tid >> 3)) & 3u) * 16u;
    const size_t offA = ((size_t)a * 64 + (tid >> 2)) * DD + (tid & 3) * 8;
    const size_t offB = ((size_t)b * 64 + (tid >> 2)) * DD + (tid & 3) * 8;
    const __nv_bfloat16* hiA = hi_n + offA;
    const __nv_bfloat16* loA = lo_n + offA;
    const __nv_bfloat16* hiB = hi_n + offB;
    const __nv_bfloat16* loB = lo_n + offB;

#define LOAD_CHUNK(bufoff, k0) do {                                            \
    const uint32_t d_ = base_dst + (bufoff);                                   \
    cp16(d_ +     0, hiA + (k0));            cp16(d_ +  2048, hiA + 32*DD + (k0)); \
    cp16(d_ +  4096, loA + (k0));            cp16(d_ +  6144, loA + 32*DD + (k0)); \
    if (!diag) {                                                               \
        cp16(d_ +  8192, hiB + (k0));        cp16(d_ + 10240, hiB + 32*DD + (k0)); \
        cp16(d_ + 12288, loB + (k0));        cp16(d_ + 14336, loB + 32*DD + (k0)); \
    }                                                                          \
} while (0)

    // ---- prologue: sq + k-chunk 0 (one commit group) ----
    if (tid < 32) {
        int grp = (tid < 16) ? a : b;
        int q = tid & 15;
        cp16(sb + SM_SQ + tid * 16, g_sq + n * MM + grp * 64 + q * 4);
    }
    LOAD_CHUNK(0, 0);
    CP_COMMIT();

    const uint32_t bplane = diag ? 0u : 2u * PLANE;

    // per-lane ldmatrix swizzle constants
    const int la = lane & 15;
    const uint32_t aro = (uint32_t)la * 64;
    const int xa = (la >> 1) & 3;
    const int pa = lane >> 4;
    const uint32_t cxa0 = (uint32_t)((pa ^ xa) & 3) << 4;
    const uint32_t cxa1 = (uint32_t)(((2 + pa) ^ xa) & 3) << 4;
    const int rbr = (lane & 7) + ((lane >> 4) & 1) * 8;
    const uint32_t bro = (uint32_t)rbr * 64;
    const int xb = (rbr >> 1) & 3;
    const int pb = (lane >> 3) & 1;
    const uint32_t cxb0 = (uint32_t)((pb ^ xb) & 3) << 4;
    const uint32_t cxb1 = (uint32_t)(((2 + pb) ^ xb) & 3) << 4;

    float acc[2][4][4];
#pragma unroll
    for (int mi = 0; mi < 2; mi++)
#pragma unroll
        for (int ni = 0; ni < 4; ni++)
#pragma unroll
            for (int r = 0; r < 4; r++) acc[mi][ni][r] = 0.f;

#pragma unroll 1
    for (int s = 0; s < 8; s++) {
        if (s < 7) {
            LOAD_CHUNK(((s + 1) & 1) * BUFSZ, (s + 1) * 32);
            CP_COMMIT();
            CP_WAIT(1);
        } else {
            CP_WAIT(0);
        }
        __syncthreads();

        const uint32_t bufb = sb + (uint32_t)(s & 1) * BUFSZ;
#pragma unroll
        for (int ks = 0; ks < 2; ks++) {
            const uint32_t cxa = ks ? cxa1 : cxa0;
            const uint32_t cxb = ks ? cxb1 : cxb0;
            uint32_t ahi[2][4], alo[2][4], bhi[2][4], blo[2][4];
#pragma unroll
            for (int mi = 0; mi < 2; mi++) {
                uint32_t ra = bufb + (uint32_t)(wr * 32 + mi * 16) * 64 + aro + cxa;
                ldm_x4(ahi[mi], ra);
                ldm_x4(alo[mi], ra + PLANE);
            }
#pragma unroll
            for (int g = 0; g < 2; g++) {
                uint32_t rbad = bufb + bplane + (uint32_t)(wc * 32 + g * 16) * 64 + bro + cxb;
                ldm_x4(bhi[g], rbad);
                ldm_x4(blo[g], rbad + PLANE);
            }
#pragma unroll
            for (int mi = 0; mi < 2; mi++)
#pragma unroll
                for (int ni = 0; ni < 4; ni++) {
                    const int g = ni >> 1, o = (ni & 1) * 2;
                    mma16816(acc[mi][ni], ahi[mi], &bhi[g][o]);
                    mma16816(acc[mi][ni], ahi[mi], &blo[g][o]);
                    mma16816(acc[mi][ni], alo[mi], &bhi[g][o]);
                }
        }
        __syncthreads();   // all warps done reading buf s&1 before refill
    }

    // ---- epilogue ----
    const float* sq_s = (const float*)(smem + SM_SQ);
    float rmin[4], rmax[4], cmin[8];
#pragma unroll
    for (int i = 0; i < 4; i++) { rmin[i] = FLT_MAX; rmax[i] = -FLT_MAX; }
#pragma unroll
    for (int i = 0; i < 8; i++) cmin[i] = FLT_MAX;
    float dsum = 0.f;

#pragma unroll
    for (int mi = 0; mi < 2; mi++)
#pragma unroll
        for (int ni = 0; ni < 4; ni++)
#pragma unroll
            for (int r = 0; r < 4; r++) {
                const int rowl = wr * 32 + mi * 16 + (r >> 1) * 8 + (lane >> 2);
                const int col  = wc * 32 + ni * 8 + (lane & 3) * 2 + (r & 1);
                float d2 = sq_s[rowl] + sq_s[64 + col] - 2.f * acc[mi][ni][r];
                float dist = sqrtf(fmaxf(d2, 0.f));
                dsum += dist;
                const int rs = mi * 2 + (r >> 1);
                const int cs = ni * 2 + (r & 1);
                if (diag) {
                    if ((rowl >> 3) == (col >> 3)) rmax[rs] = fmaxf(rmax[rs], dist);
                    else                           rmin[rs] = fminf(rmin[rs], dist);
                } else {
                    rmin[rs] = fminf(rmin[rs], dist);
                    cmin[cs] = fminf(cmin[cs], dist);
                }
            }

    float* rowmin = (float*)(smem + SM_ROWMIN);
    float* rowmax = (float*)(smem + SM_ROWMAX);
    float* colmin = (float*)(smem + SM_COLMIN);
    float* scratch = (float*)(smem + SM_RSUM);

#pragma unroll
    for (int s2 = 0; s2 < 4; s2++) {
        float rm = rmin[s2], rx = rmax[s2];
        rm = fminf(rm, __shfl_xor_sync(0xFFFFFFFFu, rm, 1));
        rm = fminf(rm, __shfl_xor_sync(0xFFFFFFFFu, rm, 2));
        rx = fmaxf(rx, __shfl_xor_sync(0xFFFFFFFFu, rx, 1));
        rx = fmaxf(rx, __shfl_xor_sync(0xFFFFFFFFu, rx, 2));
        if ((lane & 3) == 0) {
            const int row = wr * 32 + (s2 >> 1) * 16 + (s2 & 1) * 8 + (lane >> 2);
            rowmin[row * 2 + wc] = rm;
            rowmax[row * 2 + wc] = rx;
        }
    }
#pragma unroll
    for (int s2 = 0; s2 < 8; s2++) {
        float cm = cmin[s2];
        cm = fminf(cm, __shfl_xor_sync(0xFFFFFFFFu, cm, 4));
        cm = fminf(cm, __shfl_xor_sync(0xFFFFFFFFu, cm, 8));
        cm = fminf(cm, __shfl_xor_sync(0xFFFFFFFFu, cm, 16));
        if (lane < 4) {
            const int col = wc * 32 + (s2 >> 1) * 8 + (lane & 3) * 2 + (s2 & 1);
            colmin[col * 2 + wr] = cm;
        }
    }
#pragma unroll
    for (int o = 16; o; o >>= 1) dsum += __shfl_xor_sync(0xFFFFFFFFu, dsum, o);
    if (lane == 0) scratch[wid] = dsum;
    __syncthreads();

    if (tid < 64) {
        float rn = fminf(rowmin[tid * 2], rowmin[tid * 2 + 1]);
        float rp = fmaxf(rowmax[tid * 2], rowmax[tid * 2 + 1]);
        g_min[(n * 64 + a * 8 + b) * 64 + tid] = rn;       // slot b of group a
        if (diag) g_hp[n * MM + a * 64 + tid] = rp;
    } else {
        if (!diag) {
            const int j = tid - 64;
            float cm = fminf(colmin[j * 2], colmin[j * 2 + 1]);
            g_min[(n * 64 + b * 8 + a) * 64 + j] = cm;     // slot a of group b
        }
    }
    if (tid == 0)
        g_dsum[n * NTILE + t] = (scratch[0] + scratch[1]) + (scratch[2] + scratch[3]);

    // ---- last-CTA-per-part fused finish ----
    int* flag = (int*)(scratch + 4);
    if (tid == 0) {
        __threadfence();
        int prev = atomicAdd(&g_cnt[n], 1);
        *flag = (prev == NTILE - 1);
    }
    __syncthreads();
    if (!*flag) return;
    __threadfence();

    float l = 0.f;
#pragma unroll
    for (int h = 0; h < 4; h++) {
        const int row = tid + h * 128;
        const int g = row >> 6, j = row & 63;
        float mn = FLT_MAX;
#pragma unroll
        for (int s = 0; s < 8; s++)
            mn = fminf(mn, g_min[(n * 64 + g * 8 + s) * 64 + j]);
        l += fmaxf(MARGIN + g_hp[n * MM + row] - mn, 0.f);
    }
#pragma unroll
    for (int o = 16; o; o >>= 1) l += __shfl_xor_sync(0xFFFFFFFFu, l, o);
    if (lane == 0) scratch[wid] = l;
    if (tid < NTILE) {
        int aa, bb; tile_pair(tid, aa, bb);
        scratch[8 + tid] = g_dsum[n * NTILE + tid] * ((aa == bb) ? 1.f : 2.f);
    }
    __syncthreads();
    if (tid == 0) {
        float ls = (scratch[0] + scratch[1]) + (scratch[2] + scratch[3]);
        float d = 0.f;
#pragma unroll
        for (int i = 0; i < NTILE; i++) d += scratch[8 + i];
        out[n]         = ls / (float)MM;
        out[NPART + n] = d / ((float)MM * (float)MM);
        g_cnt[n] = 0;   // reset for next graph replay
    }
}

extern "C" void kernel_launch(void* const* d_in, const int* in_sizes, int n_in,
                              void* d_out, int out_size) {
    const float* feature = (const float*)d_in[0];
    float* out = (float*)d_out;

    cudaFuncSetAttribute(gemm_kernel, cudaFuncAttributeMaxDynamicSharedMemorySize, SM_TOTAL);

    dim3 b1(32, 8);
    prep_kernel<<<(NPART * MM + 7) / 8, b1>>>(feature);

    dim3 grid(NTILE, NPART);
    gemm_kernel<<<grid, 128, SM_TOTAL>>>(out);
}